// round 1
// baseline (speedup 1.0000x reference)
#include <cuda_runtime.h>

#define NN 8192
#define BLOCK 256
#define RPB 64                      // rows per block
#define GRID (NN / RPB)             // 128 blocks
#define CHUNKS (NN / (BLOCK * 4))   // 8 float4 chunks per thread
#define RU 4                        // rows processed per p-load

// scratch (allocation-free rule: __device__ globals)
__device__ float g_p0[NN], g_p1[NN], g_p2[NN];
__device__ float g_deg[NN];
__device__ float g_dot[NN * 3];

__global__ void prep_kernel(const float* __restrict__ pred1,
                            const float* __restrict__ pred2) {
    int i = blockIdx.x * blockDim.x + threadIdx.x;
    if (i < NN) {
        g_p0[i] = pred2[3 * i + 0] - pred1[3 * i + 0];
        g_p1[i] = pred2[3 * i + 1] - pred1[3 * i + 1];
        g_p2[i] = pred2[3 * i + 2] - pred1[3 * i + 2];
        g_deg[i] = 0.0f;
    }
}

// One pass over A: per-row dot with p (D=3) + column sums (deg).
__global__ __launch_bounds__(BLOCK, 1)
void spmm_kernel(const float* __restrict__ A) {
    extern __shared__ float smem[];
    float* sp0 = smem;
    float* sp1 = smem + NN;
    float* sp2 = smem + 2 * NN;
    float* red = smem + 3 * NN;      // 8 warps * 12 floats

    const int tid  = threadIdx.x;
    const int lane = tid & 31;
    const int warp = tid >> 5;

    // stage p into smem (SoA)
    for (int i = tid; i < NN; i += BLOCK) {
        sp0[i] = g_p0[i];
        sp1[i] = g_p1[i];
        sp2[i] = g_p2[i];
    }
    __syncthreads();

    const int row0 = blockIdx.x * RPB;

    float degLocal[CHUNKS * 4];
    #pragma unroll
    for (int i = 0; i < CHUNKS * 4; i++) degLocal[i] = 0.0f;

    for (int rg = 0; rg < RPB; rg += RU) {
        float acc[RU][3];
        #pragma unroll
        for (int r = 0; r < RU; r++) {
            acc[r][0] = 0.0f; acc[r][1] = 0.0f; acc[r][2] = 0.0f;
        }

        #pragma unroll
        for (int c = 0; c < CHUNKS; c++) {
            const int col = (c * BLOCK + tid) * 4;
            const float4 pa = *reinterpret_cast<const float4*>(&sp0[col]);
            const float4 pb = *reinterpret_cast<const float4*>(&sp1[col]);
            const float4 pc = *reinterpret_cast<const float4*>(&sp2[col]);

            #pragma unroll
            for (int r = 0; r < RU; r++) {
                const size_t off = (size_t)(row0 + rg + r) * NN + col;
                const float4 a = *reinterpret_cast<const float4*>(&A[off]);
                acc[r][0] += a.x * pa.x + a.y * pa.y + a.z * pa.z + a.w * pa.w;
                acc[r][1] += a.x * pb.x + a.y * pb.y + a.z * pb.z + a.w * pb.w;
                acc[r][2] += a.x * pc.x + a.y * pc.y + a.z * pc.z + a.w * pc.w;
                degLocal[c * 4 + 0] += a.x;
                degLocal[c * 4 + 1] += a.y;
                degLocal[c * 4 + 2] += a.z;
                degLocal[c * 4 + 3] += a.w;
            }
        }

        // block-reduce the 12 row partials
        #pragma unroll
        for (int r = 0; r < RU; r++) {
            #pragma unroll
            for (int d = 0; d < 3; d++) {
                float v = acc[r][d];
                v += __shfl_down_sync(0xFFFFFFFFu, v, 16);
                v += __shfl_down_sync(0xFFFFFFFFu, v, 8);
                v += __shfl_down_sync(0xFFFFFFFFu, v, 4);
                v += __shfl_down_sync(0xFFFFFFFFu, v, 2);
                v += __shfl_down_sync(0xFFFFFFFFu, v, 1);
                if (lane == 0) red[warp * 12 + r * 3 + d] = v;
            }
        }
        __syncthreads();
        if (tid < 12) {
            float v = 0.0f;
            #pragma unroll
            for (int w = 0; w < BLOCK / 32; w++) v += red[w * 12 + tid];
            const int r = tid / 3;
            const int d = tid - r * 3;
            g_dot[(row0 + rg + r) * 3 + d] = v;
        }
        __syncthreads();
    }

    // flush deg partials (spread addresses within a warp -> fast L2 atomics)
    #pragma unroll
    for (int c = 0; c < CHUNKS; c++) {
        const int col = (c * BLOCK + tid) * 4;
        atomicAdd(&g_deg[col + 0], degLocal[c * 4 + 0]);
        atomicAdd(&g_deg[col + 1], degLocal[c * 4 + 1]);
        atomicAdd(&g_deg[col + 2], degLocal[c * 4 + 2]);
        atomicAdd(&g_deg[col + 3], degLocal[c * 4 + 3]);
    }
}

__global__ void loss_kernel(float* __restrict__ out) {
    __shared__ float red[BLOCK / 32];
    const int tid  = threadIdx.x;
    const int lane = tid & 31;
    const int warp = tid >> 5;

    float s = 0.0f;
    for (int i = tid; i < NN; i += BLOCK) {
        const float inv = 1.0f / g_deg[i];
        const float d0 = g_p0[i] - g_dot[3 * i + 0] * inv;
        const float d1 = g_p1[i] - g_dot[3 * i + 1] * inv;
        const float d2 = g_p2[i] - g_dot[3 * i + 2] * inv;
        s += d0 * d0 + d1 * d1 + d2 * d2;
    }
    s += __shfl_down_sync(0xFFFFFFFFu, s, 16);
    s += __shfl_down_sync(0xFFFFFFFFu, s, 8);
    s += __shfl_down_sync(0xFFFFFFFFu, s, 4);
    s += __shfl_down_sync(0xFFFFFFFFu, s, 2);
    s += __shfl_down_sync(0xFFFFFFFFu, s, 1);
    if (lane == 0) red[warp] = s;
    __syncthreads();
    if (tid == 0) {
        float v = 0.0f;
        #pragma unroll
        for (int w = 0; w < BLOCK / 32; w++) v += red[w];
        out[0] = v;
    }
}

extern "C" void kernel_launch(void* const* d_in, const int* in_sizes, int n_in,
                              void* d_out, int out_size) {
    const float* pred1 = (const float*)d_in[0];
    const float* pred2 = (const float*)d_in[1];
    const float* A     = (const float*)d_in[2];
    float* out = (float*)d_out;

    const int smem_bytes = (3 * NN + 12 * (BLOCK / 32)) * (int)sizeof(float);
    cudaFuncSetAttribute(spmm_kernel,
                         cudaFuncAttributeMaxDynamicSharedMemorySize, smem_bytes);

    prep_kernel<<<(NN + 255) / 256, 256>>>(pred1, pred2);
    spmm_kernel<<<GRID, BLOCK, smem_bytes>>>(A);
    loss_kernel<<<1, BLOCK>>>(out);
}